// round 3
// baseline (speedup 1.0000x reference)
#include <cuda_runtime.h>
#include <cuda_fp16.h>
#include <cstdint>

#define SEQ   256
#define HID   512
#define NOUT  128
#define NB    512
#define NBLK  128          // 4 m-tiles x 32 j-tiles
#define NTHR  256
#define DYN_SMEM 131072    // A tile: 128 rows x 512 fp16 (1KB/row), swizzled

// ------------------------- device globals (scratch) --------------------------
__device__ __half  g_hbuf[2][NB * HID];   // ping-pong h (fp16, row-major [batch][hid])
__device__ float   g_hfin[NB * HID];      // final h (fp32) for projection
__device__ unsigned g_count = 0;
__device__ unsigned g_gen   = 0;

// ------------------------------ PTX helpers ----------------------------------
__device__ __forceinline__ uint32_t smem_u32(const void* p) {
    uint32_t a;
    asm("{ .reg .u64 t; cvta.to.shared.u64 t, %1; cvt.u32.u64 %0, t; }" : "=r"(a) : "l"(p));
    return a;
}

__device__ __forceinline__ void ldsm_x4(uint32_t& a0, uint32_t& a1, uint32_t& a2, uint32_t& a3,
                                        uint32_t addr) {
    asm volatile("ldmatrix.sync.aligned.m8n8.x4.shared.b16 {%0,%1,%2,%3}, [%4];"
                 : "=r"(a0), "=r"(a1), "=r"(a2), "=r"(a3) : "r"(addr));
}

__device__ __forceinline__ void mma16816(float* d, const uint32_t* a, const uint32_t* b) {
    asm volatile(
        "mma.sync.aligned.m16n8k16.row.col.f32.f16.f16.f32 "
        "{%0,%1,%2,%3}, {%4,%5,%6,%7}, {%8,%9}, {%0,%1,%2,%3};"
        : "+f"(d[0]), "+f"(d[1]), "+f"(d[2]), "+f"(d[3])
        : "r"(a[0]), "r"(a[1]), "r"(a[2]), "r"(a[3]), "r"(b[0]), "r"(b[1]));
}

__device__ __forceinline__ float sigf(float v) {
    return __fdividef(1.f, 1.f + __expf(-v));
}

// ----------------------------- grid barrier ----------------------------------
__device__ __forceinline__ void grid_bar(unsigned gbase, unsigned target) {
    __syncthreads();
    if (threadIdx.x == 0) {
        __threadfence();
        unsigned old = atomicAdd(&g_count, 1u);
        if (old == (unsigned)NBLK - 1u) {
            *(volatile unsigned*)&g_count = 0u;
            __threadfence();
            atomicAdd(&g_gen, 1u);
        } else {
            while (true) {
                unsigned g = *(volatile unsigned*)&g_gen;
                if (g - gbase >= target) break;
                __nanosleep(32);
            }
        }
        __threadfence();
    }
    __syncthreads();
}

// ------------------------- persistent LSTM kernel ----------------------------
__global__ void __launch_bounds__(NTHR, 1) lstm_persistent(
    const float* __restrict__ x,
    const float* __restrict__ Wgx, const float* __restrict__ bgx,
    const float* __restrict__ Wgh, const float* __restrict__ bgh,
    const float* __restrict__ Wix, const float* __restrict__ bix,
    const float* __restrict__ Wih, const float* __restrict__ bih,
    const float* __restrict__ Wfx, const float* __restrict__ bfx,
    const float* __restrict__ Wfh, const float* __restrict__ bfh,
    const float* __restrict__ Wox, const float* __restrict__ box_,
    const float* __restrict__ Woh, const float* __restrict__ boh)
{
    extern __shared__ char sA[];
    const uint32_t sb = smem_u32(sA);

    const int tid  = threadIdx.x;
    const int wid  = tid >> 5;
    const int lane = tid & 31;
    const int bid  = blockIdx.x;
    const int mt   = bid >> 5;        // 0..3  : 128 batch rows
    const int jt   = bid & 31;        // 0..31 : 16 hidden outputs (64 gate cols)
    const int warpM = wid & 1;        // 2 m-groups of 64 rows
    const int warpN = wid >> 1;       // 4 n-groups of 16 cols

    const unsigned gbase = *(volatile unsigned*)&g_gen;

    // ---- zero my slice of g_hbuf[0] (h_{-1} = 0) ----------------------------
    ((uint4*)&g_hbuf[0][0])[bid * NTHR + tid] = make_uint4(0u, 0u, 0u, 0u);

    // ---- load weight fragments into registers (constant across all steps) ---
    // mma m16n8k16 B-frag: thread holds B[k][n] with n = lane/4,
    //   reg0: k = 2*(lane%4), 2*(lane%4)+1 ; reg1: same + 8.
    // Column mapping inside the CTA's 64 cols: col = 4*j_local + gate (g,i,f,o).
    uint32_t breg[2][32][2];
    {
        #pragma unroll
        for (int nf = 0; nf < 2; nf++) {
            int colc = warpN * 16 + nf * 8 + (lane >> 2);
            int gate = colc & 3;
            int jg   = jt * 16 + (colc >> 2);
            const float* W = (gate == 0) ? Wgh : (gate == 1) ? Wih
                           : (gate == 2) ? Wfh : Woh;
            const float* wr = W + (size_t)jg * HID;
            #pragma unroll
            for (int kf = 0; kf < 32; kf++) {
                int k0 = kf * 16 + (lane & 3) * 2;
                float2 lo = __ldg((const float2*)(wr + k0));
                float2 hi = __ldg((const float2*)(wr + k0 + 8));
                __half2 l2 = __floats2half2_rn(lo.x, lo.y);
                __half2 h2 = __floats2half2_rn(hi.x, hi.y);
                breg[nf][kf][0] = *(uint32_t*)&l2;
                breg[nf][kf][1] = *(uint32_t*)&h2;
            }
        }
    }

    // ---- per-thread epilogue constants (x-weight + fused bias) --------------
    // Accum cols for this thread: 2c, 2c+1 with c = lane&3.
    //   c even -> (g, i) of j ; c odd -> (f, o) of j.  Pair partner = lane^1.
    const int cpar = lane & 3;
    const bool evenc = ((cpar & 1) == 0);
    float wA[2], bA[2], wB[2], bB[2];   // per nfrag: gate pair consts
    #pragma unroll
    for (int nf = 0; nf < 2; nf++) {
        int jg = jt * 16 + warpN * 4 + nf * 2 + (cpar >> 1);
        if (evenc) {
            wA[nf] = __ldg(&Wgx[jg]); bA[nf] = __ldg(&bgx[jg]) + __ldg(&bgh[jg]);
            wB[nf] = __ldg(&Wix[jg]); bB[nf] = __ldg(&bix[jg]) + __ldg(&bih[jg]);
        } else {
            wA[nf] = __ldg(&Wfx[jg]); bA[nf] = __ldg(&bfx[jg]) + __ldg(&bfh[jg]);
            wB[nf] = __ldg(&Wox[jg]); bB[nf] = __ldg(&box_[jg]) + __ldg(&boh[jg]);
        }
    }
    const float sc  = evenc ? 2.f : 1.f;
    const float sc1 = sc - 1.f;

    // ---- address precompute --------------------------------------------------
    // copy: per i (0..3): row = i*32 + r0, kc = ch*8 + k0  (uint4 = 16B chunk)
    const int r0 = tid >> 3;          // 0..31
    const int k0c = tid & 7;
    const int s0 = r0 & 7;
    const uint32_t sts_base = sb + (uint32_t)r0 * 1024u + (uint32_t)(k0c ^ s0) * 16u;
    // ldmatrix: row = warpM*64 + mf*16 + (lane&15), kc = kfg*2 + (lane>>4)
    const int lrow = warpM * 64 + (lane & 15);
    const int s2   = lane & 7;
    const int hi4  = lane >> 4;
    const uint32_t lds_base = sb + (uint32_t)lrow * 1024u;

    // h-state write j (odd threads own cell state)
    int jh[2];
    #pragma unroll
    for (int nf = 0; nf < 2; nf++) jh[nf] = jt * 16 + warpN * 4 + nf * 2 + (cpar >> 1);

    // all h-zero writes visible chip-wide before step 0
    grid_bar(gbase, 1u);

    float cst[4][2][2];               // [mf][nf][half] (odd threads)
    #pragma unroll
    for (int mf = 0; mf < 4; mf++)
        #pragma unroll
        for (int nf = 0; nf < 2; nf++) { cst[mf][nf][0] = 0.f; cst[mf][nf][1] = 0.f; }

    // ---- main recurrence -----------------------------------------------------
    for (int t = 0; t < SEQ; t++) {
        const int p = t & 1;
        const uint4* __restrict__ src = (const uint4*)&g_hbuf[p][0]
                                      + (size_t)(mt * 128 + r0) * 64 + k0c;

        float acc[4][2][4];
        #pragma unroll
        for (int mf = 0; mf < 4; mf++)
            #pragma unroll
            for (int nf = 0; nf < 2; nf++)
                #pragma unroll
                for (int q = 0; q < 4; q++) acc[mf][nf][q] = 0.f;

        float xv[8];

        // prefetch chunk 0
        uint4 buf[4];
        #pragma unroll
        for (int i = 0; i < 4; i++) buf[i] = __ldcg(src + (size_t)i * 2048);

        #pragma unroll
        for (int ch = 0; ch < 8; ch++) {
            // stage chunk ch
            #pragma unroll
            for (int i = 0; i < 4; i++)
                *(uint4*)(sA + (sts_base - sb) + (uint32_t)i * 32768u + (uint32_t)ch * 128u) = buf[i];
            __syncthreads();

            // issue next chunk's loads (overlap with HMMA below)
            if (ch < 7) {
                #pragma unroll
                for (int i = 0; i < 4; i++)
                    buf[i] = __ldcg(src + (size_t)i * 2048 + (ch + 1) * 8);
            }
            if (ch == 0) {
                // prefetch x_t for this thread's 8 rows
                #pragma unroll
                for (int mf = 0; mf < 4; mf++)
                    #pragma unroll
                    for (int hf = 0; hf < 2; hf++) {
                        int row = warpM * 64 + mf * 16 + (lane >> 2) + hf * 8;
                        xv[mf * 2 + hf] = __ldg(&x[(size_t)(mt * 128 + row) * SEQ + t]);
                    }
            }

            // HMMA over this chunk's 4 k-frags
            #pragma unroll
            for (int kf = 0; kf < 4; kf++) {
                const int kfg = ch * 4 + kf;
                uint32_t afr[4][4];
                #pragma unroll
                for (int mf = 0; mf < 4; mf++) {
                    uint32_t idx = (uint32_t)(((kfg << 1) | hi4) ^ s2);
                    uint32_t addr = lds_base + (uint32_t)mf * 16384u + (idx << 4);
                    ldsm_x4(afr[mf][0], afr[mf][1], afr[mf][2], afr[mf][3], addr);
                }
                #pragma unroll
                for (int mf = 0; mf < 4; mf++)
                    #pragma unroll
                    for (int nf = 0; nf < 2; nf++)
                        mma16816(acc[mf][nf], afr[mf], breg[nf][kfg]);
            }
        }

        // ---- epilogue: gates -> c,h -----------------------------------------
        #pragma unroll
        for (int mf = 0; mf < 4; mf++) {
            const float x0 = xv[mf * 2], x1 = xv[mf * 2 + 1];
            #pragma unroll
            for (int nf = 0; nf < 2; nf++) {
                float a0 = acc[mf][nf][0] + x0 * wA[nf] + bA[nf];
                float a1 = acc[mf][nf][1] + x0 * wB[nf] + bB[nf];
                float a2 = acc[mf][nf][2] + x1 * wA[nf] + bA[nf];
                float a3 = acc[mf][nf][3] + x1 * wB[nf] + bB[nf];
                // even: val0 = tanh(a0) = 2*sig(2a0)-1 ; odd: val0 = sig(a0)
                float v0 = sigf(sc * a0) * sc - sc1;
                float v2 = sigf(sc * a2) * sc - sc1;
                float v1 = sigf(a1);
                float v3 = sigf(a3);
                float s0v = v0 * v1;                 // (even) tanh(g)*sig(i) row0
                float s1v = v2 * v3;                 // row1
                float r0v = __shfl_xor_sync(0xffffffffu, s0v, 1);
                float r1v = __shfl_xor_sync(0xffffffffu, s1v, 1);
                if (!evenc) {
                    float c0 = cst[mf][nf][0] * v0 + r0v;   // v0 = sig(f) row0
                    float c1 = cst[mf][nf][1] * v2 + r1v;
                    cst[mf][nf][0] = c0;
                    cst[mf][nf][1] = c1;
                    float h0 = (2.f * sigf(2.f * c0) - 1.f) * v1;  // tanh(c)*sig(o)
                    float h1 = (2.f * sigf(2.f * c1) - 1.f) * v3;
                    int row0 = mt * 128 + warpM * 64 + mf * 16 + (lane >> 2);
                    if (t < SEQ - 1) {
                        g_hbuf[p ^ 1][(size_t)row0 * HID + jh[nf]]       = __float2half_rn(h0);
                        g_hbuf[p ^ 1][(size_t)(row0 + 8) * HID + jh[nf]] = __float2half_rn(h1);
                    } else {
                        g_hfin[(size_t)row0 * HID + jh[nf]]       = h0;
                        g_hfin[(size_t)(row0 + 8) * HID + jh[nf]] = h1;
                    }
                }
            }
        }

        if (t < SEQ - 1) grid_bar(gbase, (unsigned)(t + 2));
    }
}

// ------------------------ projection + softmax -------------------------------
__global__ void __launch_bounds__(NOUT) proj_kernel(const float* __restrict__ Wp,
                                                    const float* __restrict__ bp,
                                                    float* __restrict__ out)
{
    __shared__ float sh[HID];
    __shared__ float sred[NOUT];
    const int b = blockIdx.x, tid = threadIdx.x;

    ((float4*)sh)[tid] = ((const float4*)(g_hfin + (size_t)b * HID))[tid];
    __syncthreads();

    float acc = __ldg(&bp[tid]);
    const float4* w = (const float4*)(Wp + (size_t)tid * HID);
    #pragma unroll 8
    for (int k = 0; k < HID / 4; k++) {
        float4 wv = __ldg(w + k);
        float4 hv = ((const float4*)sh)[k];
        acc += wv.x * hv.x + wv.y * hv.y + wv.z * hv.z + wv.w * hv.w;
    }

    sred[tid] = acc;
    __syncthreads();
    for (int s = NOUT / 2; s > 0; s >>= 1) {
        if (tid < s) sred[tid] = fmaxf(sred[tid], sred[tid + s]);
        __syncthreads();
    }
    float mx = sred[0];
    __syncthreads();
    float e = __expf(acc - mx);
    sred[tid] = e;
    __syncthreads();
    for (int s = NOUT / 2; s > 0; s >>= 1) {
        if (tid < s) sred[tid] += sred[tid + s];
        __syncthreads();
    }
    out[(size_t)b * NOUT + tid] = e * __fdividef(1.f, sred[0]);
}

// ------------------------------- launch --------------------------------------
extern "C" void kernel_launch(void* const* d_in, const int* in_sizes, int n_in,
                              void* d_out, int out_size)
{
    const float* x   = (const float*)d_in[0];
    const float* Wgx = (const float*)d_in[1];
    const float* bgx = (const float*)d_in[2];
    const float* Wgh = (const float*)d_in[3];
    const float* bgh = (const float*)d_in[4];
    const float* Wix = (const float*)d_in[5];
    const float* bix = (const float*)d_in[6];
    const float* Wih = (const float*)d_in[7];
    const float* bih = (const float*)d_in[8];
    const float* Wfx = (const float*)d_in[9];
    const float* bfx = (const float*)d_in[10];
    const float* Wfh = (const float*)d_in[11];
    const float* bfh = (const float*)d_in[12];
    const float* Wox = (const float*)d_in[13];
    const float* box_= (const float*)d_in[14];
    const float* Woh = (const float*)d_in[15];
    const float* boh = (const float*)d_in[16];
    const float* Wp  = (const float*)d_in[17];
    const float* bp  = (const float*)d_in[18];
    float* out = (float*)d_out;

    static int attr_done = 0;
    (void)attr_done;
    cudaFuncSetAttribute(lstm_persistent,
                         cudaFuncAttributeMaxDynamicSharedMemorySize, DYN_SMEM);

    lstm_persistent<<<NBLK, NTHR, DYN_SMEM>>>(
        x, Wgx, bgx, Wgh, bgh, Wix, bix, Wih, bih,
        Wfx, bfx, Wfh, bfh, Wox, box_, Woh, boh);

    proj_kernel<<<NB, NOUT>>>(Wp, bp, out);
}